// round 1
// baseline (speedup 1.0000x reference)
#include <cuda_runtime.h>
#include <cstdint>
#include <cstddef>

#define S_LEN   2048
#define HID     3584
#define NH      28
#define NKV     4
#define HD      128
#define BATCH   2
#define M_TOK   (BATCH * S_LEN)      // 4096
#define SCALE_Q 0.08838834764831845f // 1/sqrt(128)

// ---------------- scratch (no allocation allowed) ----------------
__device__ float g_Q[(size_t)BATCH * NH * S_LEN * HD];    // [B, H, S, D]
__device__ float g_K[(size_t)BATCH * NKV * S_LEN * HD];   // [B, KVH, S, D]
__device__ float g_V[(size_t)BATCH * NKV * S_LEN * HD];   // [B, KVH, S, D]
__device__ float g_attn[(size_t)M_TOK * HID];             // [tok, H*D]

// ---------------- tf32 helpers ----------------
__device__ __forceinline__ uint32_t f2tf32(float x) {
    uint32_t r;
    asm("cvt.rna.tf32.f32 %0, %1;" : "=r"(r) : "f"(x));
    return r;
}

__device__ __forceinline__ void mma_tf32(float* c, const uint32_t* a, const uint32_t* b) {
    asm volatile(
        "mma.sync.aligned.m16n8k8.row.col.f32.tf32.tf32.f32 "
        "{%0,%1,%2,%3},{%4,%5,%6,%7},{%8,%9},{%0,%1,%2,%3};"
        : "+f"(c[0]), "+f"(c[1]), "+f"(c[2]), "+f"(c[3])
        : "r"(a[0]), "r"(a[1]), "r"(a[2]), "r"(a[3]), "r"(b[0]), "r"(b[1]));
}

// ---------------- GEMM: C = A(MxK,row) * Bw(NxK,row)^T + bias ----------------
// OUT_MODE 0: C[m*N + n]
// OUT_MODE 1: head layout C[((b*(N/128) + h)*2048 + s)*128 + d], m=b*2048+s, n=h*128+d
template <int OUT_MODE>
__global__ __launch_bounds__(256, 2)
void gemm_tf32(const float* __restrict__ A, const float* __restrict__ Bw,
               const float* __restrict__ bias, float* __restrict__ C,
               int M, int N, int K) {
    __shared__ uint32_t As[128][36];
    __shared__ uint32_t Bs[128][36];

    const int tid  = threadIdx.x;
    const int warp = tid >> 5;
    const int lane = tid & 31;
    const int wm   = warp >> 1;   // 0..3
    const int wn   = warp & 1;    // 0..1
    const int bm   = blockIdx.y * 128;
    const int bn   = blockIdx.x * 128;

    float acc[2][8][4];
#pragma unroll
    for (int mt = 0; mt < 2; mt++)
#pragma unroll
        for (int nt = 0; nt < 8; nt++)
#pragma unroll
            for (int i = 0; i < 4; i++) acc[mt][nt][i] = 0.f;

    for (int k0 = 0; k0 < K; k0 += 32) {
        // load A tile 128x32 (4 float4 per thread)
#pragma unroll
        for (int i = 0; i < 4; i++) {
            int f = tid + i * 256;
            int row = f >> 3, c4 = f & 7;
            float4 v = *(const float4*)(A + (size_t)(bm + row) * K + k0 + c4 * 4);
            uint32_t* dst = &As[row][c4 * 4];
            dst[0] = f2tf32(v.x); dst[1] = f2tf32(v.y);
            dst[2] = f2tf32(v.z); dst[3] = f2tf32(v.w);
        }
        // load B tile 128x32
#pragma unroll
        for (int i = 0; i < 4; i++) {
            int f = tid + i * 256;
            int row = f >> 3, c4 = f & 7;
            float4 v = *(const float4*)(Bw + (size_t)(bn + row) * K + k0 + c4 * 4);
            uint32_t* dst = &Bs[row][c4 * 4];
            dst[0] = f2tf32(v.x); dst[1] = f2tf32(v.y);
            dst[2] = f2tf32(v.z); dst[3] = f2tf32(v.w);
        }
        __syncthreads();

#pragma unroll
        for (int kk = 0; kk < 32; kk += 8) {
            uint32_t aF[2][4], bF[8][2];
#pragma unroll
            for (int mt = 0; mt < 2; mt++) {
                int r = wm * 32 + mt * 16 + (lane >> 2);
                int c = kk + (lane & 3);
                aF[mt][0] = As[r][c];
                aF[mt][1] = As[r + 8][c];
                aF[mt][2] = As[r][c + 4];
                aF[mt][3] = As[r + 8][c + 4];
            }
#pragma unroll
            for (int nt = 0; nt < 8; nt++) {
                int r = wn * 64 + nt * 8 + (lane >> 2);
                int c = kk + (lane & 3);
                bF[nt][0] = Bs[r][c];
                bF[nt][1] = Bs[r][c + 4];
            }
#pragma unroll
            for (int mt = 0; mt < 2; mt++)
#pragma unroll
                for (int nt = 0; nt < 8; nt++)
                    mma_tf32(acc[mt][nt], aF[mt], bF[nt]);
        }
        __syncthreads();
    }

    // epilogue
#pragma unroll
    for (int mt = 0; mt < 2; mt++) {
        int rbase = bm + wm * 32 + mt * 16 + (lane >> 2);
#pragma unroll
        for (int nt = 0; nt < 8; nt++) {
            int cbase = bn + wn * 64 + nt * 8 + ((lane & 3) << 1);
#pragma unroll
            for (int e = 0; e < 4; e++) {
                int r = rbase + ((e >> 1) << 3);  // +8 for e=2,3
                int c = cbase + (e & 1);
                float v = acc[mt][nt][e];
                if (bias) v += bias[c];
                if (OUT_MODE == 0) {
                    C[(size_t)r * N + c] = v;
                } else {
                    int b = r >> 11, s = r & 2047;
                    int h = c >> 7, d = c & 127;
                    C[((((size_t)b * (N >> 7) + h) * 2048 + s) << 7) + d] = v;
                }
            }
        }
    }
}

// ---------------- RoPE (in-place on [B, HX, S, 128]) ----------------
__global__ void rope_kernel(float* __restrict__ X, const float* __restrict__ cs,
                            const float* __restrict__ sn, int HX) {
    int idx = blockIdx.x * blockDim.x + threadIdx.x;  // over B*HX*S*64
    int d  = idx & 63;
    int s  = (idx >> 6) & (S_LEN - 1);
    int bh = idx >> 17;                // B*HX index (2048*64 = 2^17)
    int b  = bh / HX;
    int ci = ((b << 11) + s) * 128 + d;
    float c  = cs[ci];
    float si = sn[ci];
    float* p = X + (((size_t)bh << 11) + s) * 128 + d;
    float x1 = p[0], x2 = p[64];
    p[0]  = x1 * c - x2 * si;
    p[64] = x2 * c + x1 * si;
}

// ---------------- SIMT fp32 flash attention (causal, GQA) ----------------
// grid: (S/32, NH, B), block 128
__global__ __launch_bounds__(128, 5)
void flash_attn(const float* __restrict__ Q, const float* __restrict__ K,
                const float* __restrict__ V, float* __restrict__ Out) {
    __shared__ float Qs[32 * 128];   // XOR-swizzled float4 columns
    __shared__ float KVs[32 * 128];  // XOR-swizzled, holds K then V
    __shared__ float Ps[32 * 33];    // padded

    const int qb = blockIdx.x;
    const int h  = blockIdx.y;
    const int b  = blockIdx.z;
    const int kvh = h / (NH / NKV);

    const float* Qbase = Q + ((((size_t)(b * NH + h) * S_LEN) + qb * 32) << 7);
    const float* Kbase = K + (((size_t)(b * NKV + kvh) * S_LEN) << 7);
    const float* Vbase = V + (((size_t)(b * NKV + kvh) * S_LEN) << 7);

    const int t  = threadIdx.x;
    const int tq = t >> 4;  // 0..7  -> q rows 4*tq..+3
    const int tk = t & 15;  // 0..15 -> k cols 2*tk..+1, d cols 8*tk..+7

    // load Q (scaled), swizzled: 8 float4 per thread
#pragma unroll
    for (int i = 0; i < 8; i++) {
        int f = t + i * 128;
        int row = f >> 5, c = f & 31;
        float4 v = *(const float4*)(Qbase + (row << 7) + c * 4);
        v.x *= SCALE_Q; v.y *= SCALE_Q; v.z *= SCALE_Q; v.w *= SCALE_Q;
        *(float4*)&Qs[(row << 7) + ((c ^ (row & 31)) << 2)] = v;
    }

    float m_run[4], l_run[4], accO[4][8];
#pragma unroll
    for (int i = 0; i < 4; i++) {
        m_run[i] = -1e30f;
        l_run[i] = 0.f;
#pragma unroll
        for (int dd = 0; dd < 8; dd++) accO[i][dd] = 0.f;
    }

    for (int kb = 0; kb <= qb; kb++) {
        __syncthreads();  // prev iter done with KVs/Ps
        // load K block, swizzled
#pragma unroll
        for (int i = 0; i < 8; i++) {
            int f = t + i * 128;
            int row = f >> 5, c = f & 31;
            float4 v = *(const float4*)(Kbase + ((size_t)(kb * 32 + row) << 7) + c * 4);
            *(float4*)&KVs[(row << 7) + ((c ^ (row & 31)) << 2)] = v;
        }
        __syncthreads();

        // scores: 4q x 2k per thread
        float sc[4][2];
#pragma unroll
        for (int i = 0; i < 4; i++) { sc[i][0] = 0.f; sc[i][1] = 0.f; }
#pragma unroll 4
        for (int d4 = 0; d4 < 32; d4++) {
            float4 qv[4], kv[2];
#pragma unroll
            for (int i = 0; i < 4; i++) {
                int r = tq * 4 + i;
                qv[i] = *(float4*)&Qs[(r << 7) + ((d4 ^ (r & 31)) << 2)];
            }
#pragma unroll
            for (int j = 0; j < 2; j++) {
                int r = tk * 2 + j;
                kv[j] = *(float4*)&KVs[(r << 7) + ((d4 ^ (r & 31)) << 2)];
            }
#pragma unroll
            for (int i = 0; i < 4; i++)
#pragma unroll
                for (int j = 0; j < 2; j++)
                    sc[i][j] += qv[i].x * kv[j].x + qv[i].y * kv[j].y +
                                qv[i].z * kv[j].z + qv[i].w * kv[j].w;
        }

        if (kb == qb) {  // diagonal block: causal mask (local row/col compare)
#pragma unroll
            for (int i = 0; i < 4; i++)
#pragma unroll
                for (int j = 0; j < 2; j++)
                    if (tk * 2 + j > tq * 4 + i) sc[i][j] = -1e30f;
        }

        // online softmax
        float alpha[4];
#pragma unroll
        for (int i = 0; i < 4; i++) {
            float mx = fmaxf(sc[i][0], sc[i][1]);
#pragma unroll
            for (int o = 1; o < 16; o <<= 1)
                mx = fmaxf(mx, __shfl_xor_sync(0xffffffffu, mx, o));
            float mn = fmaxf(m_run[i], mx);
            alpha[i] = __expf(m_run[i] - mn);
            m_run[i] = mn;
            float ps = 0.f;
#pragma unroll
            for (int j = 0; j < 2; j++) {
                float p = __expf(sc[i][j] - mn);
                Ps[(tq * 4 + i) * 33 + tk * 2 + j] = p;
                ps += p;
            }
#pragma unroll
            for (int o = 1; o < 16; o <<= 1)
                ps += __shfl_xor_sync(0xffffffffu, ps, o);
            l_run[i] = l_run[i] * alpha[i] + ps;
        }
#pragma unroll
        for (int i = 0; i < 4; i++)
#pragma unroll
            for (int dd = 0; dd < 8; dd++) accO[i][dd] *= alpha[i];

        __syncthreads();  // Ps visible; scores done reading KVs
        // load V block into KVs, swizzled
#pragma unroll
        for (int i = 0; i < 8; i++) {
            int f = t + i * 128;
            int row = f >> 5, c = f & 31;
            float4 v = *(const float4*)(Vbase + ((size_t)(kb * 32 + row) << 7) + c * 4);
            *(float4*)&KVs[(row << 7) + ((c ^ (row & 31)) << 2)] = v;
        }
        __syncthreads();

        // PV: out rows 4*tq..+3, d cols 8*tk..+7
#pragma unroll 2
        for (int k = 0; k < 32; k++) {
            float p[4];
#pragma unroll
            for (int i = 0; i < 4; i++) p[i] = Ps[(tq * 4 + i) * 33 + k];
            float4 v0 = *(float4*)&KVs[(k << 7) + (((2 * tk)     ^ (k & 31)) << 2)];
            float4 v1 = *(float4*)&KVs[(k << 7) + (((2 * tk + 1) ^ (k & 31)) << 2)];
#pragma unroll
            for (int i = 0; i < 4; i++) {
                accO[i][0] += p[i] * v0.x; accO[i][1] += p[i] * v0.y;
                accO[i][2] += p[i] * v0.z; accO[i][3] += p[i] * v0.w;
                accO[i][4] += p[i] * v1.x; accO[i][5] += p[i] * v1.y;
                accO[i][6] += p[i] * v1.z; accO[i][7] += p[i] * v1.w;
            }
        }
    }

    // write attn output to [tok, H*D]
#pragma unroll
    for (int i = 0; i < 4; i++) {
        float inv = 1.f / l_run[i];
        size_t tok = (size_t)b * S_LEN + qb * 32 + tq * 4 + i;
        float* dst = Out + tok * HID + h * 128 + tk * 8;
        float4 o0 = make_float4(accO[i][0] * inv, accO[i][1] * inv,
                                accO[i][2] * inv, accO[i][3] * inv);
        float4 o1 = make_float4(accO[i][4] * inv, accO[i][5] * inv,
                                accO[i][6] * inv, accO[i][7] * inv);
        *(float4*)dst = o0;
        *(float4*)(dst + 4) = o1;
    }
}

// ---------------- launch ----------------
extern "C" void kernel_launch(void* const* d_in, const int* in_sizes, int n_in,
                              void* d_out, int out_size) {
    const float* X  = (const float*)d_in[0];
    const float* cs = (const float*)d_in[1];
    const float* sn = (const float*)d_in[2];
    // d_in[3] attention_mask: pure causal, handled analytically
    const float* Wq = (const float*)d_in[4];
    const float* bq = (const float*)d_in[5];
    const float* Wk = (const float*)d_in[6];
    const float* bk = (const float*)d_in[7];
    const float* Wv = (const float*)d_in[8];
    const float* bv = (const float*)d_in[9];
    const float* Wo = (const float*)d_in[10];
    float* out = (float*)d_out;

    float *Qp, *Kp, *Vp, *Ap;
    cudaGetSymbolAddress((void**)&Qp, g_Q);
    cudaGetSymbolAddress((void**)&Kp, g_K);
    cudaGetSymbolAddress((void**)&Vp, g_V);
    cudaGetSymbolAddress((void**)&Ap, g_attn);

    gemm_tf32<1><<<dim3(HID / 128, M_TOK / 128), 256>>>(X, Wq, bq, Qp, M_TOK, HID, HID);
    gemm_tf32<1><<<dim3(512 / 128, M_TOK / 128), 256>>>(X, Wk, bk, Kp, M_TOK, 512, HID);
    gemm_tf32<1><<<dim3(512 / 128, M_TOK / 128), 256>>>(X, Wv, bv, Vp, M_TOK, 512, HID);

    rope_kernel<<<(BATCH * NH * S_LEN * 64) / 256, 256>>>(Qp, cs, sn, NH);
    rope_kernel<<<(BATCH * NKV * S_LEN * 64) / 256, 256>>>(Kp, cs, sn, NKV);

    flash_attn<<<dim3(S_LEN / 32, NH, BATCH), 128>>>(Qp, Kp, Vp, Ap);

    gemm_tf32<0><<<dim3(HID / 128, M_TOK / 128), 256>>>(Ap, Wo, nullptr, out, M_TOK, HID, HID);
}

// round 2
// speedup vs baseline: 1.9527x; 1.9527x over previous
#include <cuda_runtime.h>
#include <cstdint>
#include <cstddef>

#define S_LEN   2048
#define HID     3584
#define NH      28
#define NKV     4
#define HD      128
#define BATCH   2
#define M_TOK   (BATCH * S_LEN)      // 4096
#define SCALE_Q 0.08838834764831845f // 1/sqrt(128)

// ---------------- scratch (no allocation allowed) ----------------
__device__ float g_Q[(size_t)BATCH * NH * S_LEN * HD];    // [B, H, S, D]
__device__ float g_K[(size_t)BATCH * NKV * S_LEN * HD];   // [B, KVH, S, D]
__device__ float g_V[(size_t)BATCH * NKV * S_LEN * HD];   // [B, KVH, S, D]
__device__ float g_attn[(size_t)M_TOK * HID];             // [tok, H*D]

// ---------------- tf32 helpers ----------------
__device__ __forceinline__ uint32_t f2tf32(float x) {
    uint32_t r;
    asm("cvt.rna.tf32.f32 %0, %1;" : "=r"(r) : "f"(x));
    return r;
}

__device__ __forceinline__ void mma_tf32(float* c, const uint32_t* a, const uint32_t* b) {
    asm volatile(
        "mma.sync.aligned.m16n8k8.row.col.f32.tf32.tf32.f32 "
        "{%0,%1,%2,%3},{%4,%5,%6,%7},{%8,%9},{%0,%1,%2,%3};"
        : "+f"(c[0]), "+f"(c[1]), "+f"(c[2]), "+f"(c[3])
        : "r"(a[0]), "r"(a[1]), "r"(a[2]), "r"(a[3]), "r"(b[0]), "r"(b[1]));
}

// ---------------- GEMM: C = A(MxK,row) * Bw(NxK,row)^T + bias ----------------
// OUT_MODE 0: C[m*N + n]
// OUT_MODE 1: head layout C[((b*(N/128) + h)*2048 + s)*128 + d]
template <int OUT_MODE>
__global__ __launch_bounds__(256, 2)
void gemm_tf32(const float* __restrict__ A, const float* __restrict__ Bw,
               const float* __restrict__ bias, float* __restrict__ C,
               int M, int N, int K) {
    __shared__ uint32_t As[128][36];
    __shared__ uint32_t Bs[128][36];

    const int tid  = threadIdx.x;
    const int warp = tid >> 5;
    const int lane = tid & 31;
    const int wm   = warp >> 1;
    const int wn   = warp & 1;
    const int bm   = blockIdx.y * 128;
    const int bn   = blockIdx.x * 128;

    float acc[2][8][4];
#pragma unroll
    for (int mt = 0; mt < 2; mt++)
#pragma unroll
        for (int nt = 0; nt < 8; nt++)
#pragma unroll
            for (int i = 0; i < 4; i++) acc[mt][nt][i] = 0.f;

    for (int k0 = 0; k0 < K; k0 += 32) {
#pragma unroll
        for (int i = 0; i < 4; i++) {
            int f = tid + i * 256;
            int row = f >> 3, c4 = f & 7;
            float4 v = *(const float4*)(A + (size_t)(bm + row) * K + k0 + c4 * 4);
            uint32_t* dst = &As[row][c4 * 4];
            dst[0] = f2tf32(v.x); dst[1] = f2tf32(v.y);
            dst[2] = f2tf32(v.z); dst[3] = f2tf32(v.w);
        }
#pragma unroll
        for (int i = 0; i < 4; i++) {
            int f = tid + i * 256;
            int row = f >> 3, c4 = f & 7;
            float4 v = *(const float4*)(Bw + (size_t)(bn + row) * K + k0 + c4 * 4);
            uint32_t* dst = &Bs[row][c4 * 4];
            dst[0] = f2tf32(v.x); dst[1] = f2tf32(v.y);
            dst[2] = f2tf32(v.z); dst[3] = f2tf32(v.w);
        }
        __syncthreads();

#pragma unroll
        for (int kk = 0; kk < 32; kk += 8) {
            uint32_t aF[2][4], bF[8][2];
#pragma unroll
            for (int mt = 0; mt < 2; mt++) {
                int r = wm * 32 + mt * 16 + (lane >> 2);
                int c = kk + (lane & 3);
                aF[mt][0] = As[r][c];
                aF[mt][1] = As[r + 8][c];
                aF[mt][2] = As[r][c + 4];
                aF[mt][3] = As[r + 8][c + 4];
            }
#pragma unroll
            for (int nt = 0; nt < 8; nt++) {
                int r = wn * 64 + nt * 8 + (lane >> 2);
                int c = kk + (lane & 3);
                bF[nt][0] = Bs[r][c];
                bF[nt][1] = Bs[r][c + 4];
            }
#pragma unroll
            for (int mt = 0; mt < 2; mt++)
#pragma unroll
                for (int nt = 0; nt < 8; nt++)
                    mma_tf32(acc[mt][nt], aF[mt], bF[nt]);
        }
        __syncthreads();
    }

#pragma unroll
    for (int mt = 0; mt < 2; mt++) {
        int rbase = bm + wm * 32 + mt * 16 + (lane >> 2);
#pragma unroll
        for (int nt = 0; nt < 8; nt++) {
            int cbase = bn + wn * 64 + nt * 8 + ((lane & 3) << 1);
#pragma unroll
            for (int e = 0; e < 4; e++) {
                int r = rbase + ((e >> 1) << 3);
                int c = cbase + (e & 1);
                float v = acc[mt][nt][e];
                if (bias) v += bias[c];
                if (OUT_MODE == 0) {
                    C[(size_t)r * N + c] = v;
                } else {
                    int b = r >> 11, s = r & 2047;
                    int h = c >> 7, d = c & 127;
                    C[((((size_t)b * (N >> 7) + h) * 2048 + s) << 7) + d] = v;
                }
            }
        }
    }
}

// ---------------- RoPE (in-place on [B, HX, S, 128]) ----------------
__global__ void rope_kernel(float* __restrict__ X, const float* __restrict__ cs,
                            const float* __restrict__ sn, int HX) {
    int idx = blockIdx.x * blockDim.x + threadIdx.x;
    int d  = idx & 63;
    int s  = (idx >> 6) & (S_LEN - 1);
    int bh = idx >> 17;
    int b  = bh / HX;
    int ci = ((b << 11) + s) * 128 + d;
    float c  = cs[ci];
    float si = sn[ci];
    float* p = X + (((size_t)bh << 11) + s) * 128 + d;
    float x1 = p[0], x2 = p[64];
    p[0]  = x1 * c - x2 * si;
    p[64] = x2 * c + x1 * si;
}

// ---------------- tensor-core flash attention (tf32, causal, GQA) ----------------
// grid: (S/128, NH, B), block 256 (8 warps). Tile: 128 q rows x 64 keys.
// smem (floats): Qs[128][132] @0, Ks[64][132] @16896, Vs[64][136] @25344, Ps[128][68] @34048
#define QS_STRIDE 132
#define KS_STRIDE 132
#define VS_STRIDE 136
#define PS_STRIDE 68
#define KS_OFF 16896
#define VS_OFF 25344
#define PS_OFF 34048
#define FLASH_SMEM_BYTES ((34048 + 128 * 68) * 4)  // 171008

__global__ __launch_bounds__(256, 1)
void flash_attn_tc(const float* __restrict__ Q, const float* __restrict__ K,
                   const float* __restrict__ V, float* __restrict__ Out) {
    extern __shared__ float sm[];
    float* Qs = sm;
    float* Ks = sm + KS_OFF;
    float* Vs = sm + VS_OFF;
    float* Ps = sm + PS_OFF;

    const int qb  = (gridDim.x - 1) - blockIdx.x;  // heavy blocks first
    const int h   = blockIdx.y;
    const int b   = blockIdx.z;
    const int kvh = h / (NH / NKV);

    const int t    = threadIdx.x;
    const int w    = t >> 5;
    const int lane = t & 31;
    const int lq   = lane >> 2;  // 0..7
    const int lr   = lane & 3;   // 0..3

    const float* Qg = Q + ((((size_t)(b * NH + h) * S_LEN) + qb * 128) << 7);
    const float* Kg = K + (((size_t)(b * NKV + kvh) * S_LEN) << 7);
    const float* Vg = V + (((size_t)(b * NKV + kvh) * S_LEN) << 7);

    // load + scale + cvt Q tile (128x128)
#pragma unroll
    for (int i = 0; i < 16; i++) {
        int f = i * 256 + t;
        int row = f >> 5, c4 = f & 31;
        float4 v = *(const float4*)(Qg + (row << 7) + c4 * 4);
        float4 o;
        o.x = __uint_as_float(f2tf32(v.x * SCALE_Q));
        o.y = __uint_as_float(f2tf32(v.y * SCALE_Q));
        o.z = __uint_as_float(f2tf32(v.z * SCALE_Q));
        o.w = __uint_as_float(f2tf32(v.w * SCALE_Q));
        *(float4*)(Qs + row * QS_STRIDE + c4 * 4) = o;
    }

    float m0 = -1e30f, m1 = -1e30f, l0 = 0.f, l1 = 0.f;
    float oacc[16][4];
#pragma unroll
    for (int nt = 0; nt < 16; nt++)
#pragma unroll
        for (int e = 0; e < 4; e++) oacc[nt][e] = 0.f;

    const int rbaseQ = w * 16 + lq;          // local q row (first of pair)
    const int nkb = 2 * qb + 2;

    for (int kb = 0; kb < nkb; kb++) {
        __syncthreads();
        // load K,V blocks (64x128 each)
#pragma unroll
        for (int i = 0; i < 8; i++) {
            int f = i * 256 + t;
            int row = f >> 5, c4 = f & 31;
            float4 kv = *(const float4*)(Kg + ((size_t)(kb * 64 + row) << 7) + c4 * 4);
            float4 ko;
            ko.x = __uint_as_float(f2tf32(kv.x)); ko.y = __uint_as_float(f2tf32(kv.y));
            ko.z = __uint_as_float(f2tf32(kv.z)); ko.w = __uint_as_float(f2tf32(kv.w));
            *(float4*)(Ks + row * KS_STRIDE + c4 * 4) = ko;
            float4 vv = *(const float4*)(Vg + ((size_t)(kb * 64 + row) << 7) + c4 * 4);
            float4 vo;
            vo.x = __uint_as_float(f2tf32(vv.x)); vo.y = __uint_as_float(f2tf32(vv.y));
            vo.z = __uint_as_float(f2tf32(vv.z)); vo.w = __uint_as_float(f2tf32(vv.w));
            *(float4*)(Vs + row * VS_STRIDE + c4 * 4) = vo;
        }
        __syncthreads();

        // ---- scores: S (16 x 64 per warp) = Q_w (16x128) * K^T ----
        float sacc[8][4];
#pragma unroll
        for (int nt = 0; nt < 8; nt++)
#pragma unroll
            for (int e = 0; e < 4; e++) sacc[nt][e] = 0.f;

#pragma unroll
        for (int kc = 0; kc < 16; kc++) {
            uint32_t a[4];
            const float* qp = Qs + rbaseQ * QS_STRIDE + kc * 8 + lr;
            a[0] = __float_as_uint(qp[0]);
            a[1] = __float_as_uint(qp[8 * QS_STRIDE]);
            a[2] = __float_as_uint(qp[4]);
            a[3] = __float_as_uint(qp[8 * QS_STRIDE + 4]);
#pragma unroll
            for (int nt = 0; nt < 8; nt++) {
                uint32_t bb[2];
                const float* kp = Ks + (nt * 8 + lq) * KS_STRIDE + kc * 8 + lr;
                bb[0] = __float_as_uint(kp[0]);
                bb[1] = __float_as_uint(kp[4]);
                mma_tf32(sacc[nt], a, bb);
            }
        }

        // causal mask (only near diagonal)
        if (kb >= 2 * qb) {
            int row0 = qb * 128 + rbaseQ;
#pragma unroll
            for (int nt = 0; nt < 8; nt++) {
                int key = kb * 64 + nt * 8 + lr * 2;
                if (key     > row0)     sacc[nt][0] = -1e30f;
                if (key + 1 > row0)     sacc[nt][1] = -1e30f;
                if (key     > row0 + 8) sacc[nt][2] = -1e30f;
                if (key + 1 > row0 + 8) sacc[nt][3] = -1e30f;
            }
        }

        // ---- online softmax (rows rbaseQ, rbaseQ+8) ----
        float mx0 = -1e30f, mx1 = -1e30f;
#pragma unroll
        for (int nt = 0; nt < 8; nt++) {
            mx0 = fmaxf(mx0, fmaxf(sacc[nt][0], sacc[nt][1]));
            mx1 = fmaxf(mx1, fmaxf(sacc[nt][2], sacc[nt][3]));
        }
        mx0 = fmaxf(mx0, __shfl_xor_sync(0xffffffffu, mx0, 1));
        mx0 = fmaxf(mx0, __shfl_xor_sync(0xffffffffu, mx0, 2));
        mx1 = fmaxf(mx1, __shfl_xor_sync(0xffffffffu, mx1, 1));
        mx1 = fmaxf(mx1, __shfl_xor_sync(0xffffffffu, mx1, 2));

        float mn0 = fmaxf(m0, mx0), mn1 = fmaxf(m1, mx1);
        float al0 = __expf(m0 - mn0), al1 = __expf(m1 - mn1);
        m0 = mn0; m1 = mn1;

        float s0 = 0.f, s1 = 0.f;
        float* pp0 = Ps + rbaseQ * PS_STRIDE + 2 * lr;
        float* pp1 = pp0 + 8 * PS_STRIDE;
#pragma unroll
        for (int nt = 0; nt < 8; nt++) {
            float p00 = __expf(sacc[nt][0] - mn0);
            float p01 = __expf(sacc[nt][1] - mn0);
            float p10 = __expf(sacc[nt][2] - mn1);
            float p11 = __expf(sacc[nt][3] - mn1);
            s0 += p00 + p01;
            s1 += p10 + p11;
            float2 q0, q1;
            q0.x = __uint_as_float(f2tf32(p00)); q0.y = __uint_as_float(f2tf32(p01));
            q1.x = __uint_as_float(f2tf32(p10)); q1.y = __uint_as_float(f2tf32(p11));
            *(float2*)(pp0 + nt * 8) = q0;
            *(float2*)(pp1 + nt * 8) = q1;
        }
        s0 += __shfl_xor_sync(0xffffffffu, s0, 1);
        s0 += __shfl_xor_sync(0xffffffffu, s0, 2);
        s1 += __shfl_xor_sync(0xffffffffu, s1, 1);
        s1 += __shfl_xor_sync(0xffffffffu, s1, 2);
        l0 = l0 * al0 + s0;
        l1 = l1 * al1 + s1;

#pragma unroll
        for (int nt = 0; nt < 16; nt++) {
            oacc[nt][0] *= al0; oacc[nt][1] *= al0;
            oacc[nt][2] *= al1; oacc[nt][3] *= al1;
        }

        __syncthreads();

        // ---- PV: O (16x128 per warp) += P (16x64) * V (64x128) ----
#pragma unroll
        for (int kc = 0; kc < 8; kc++) {
            uint32_t a[4];
            const float* pa = Ps + rbaseQ * PS_STRIDE + kc * 8 + lr;
            a[0] = __float_as_uint(pa[0]);
            a[1] = __float_as_uint(pa[8 * PS_STRIDE]);
            a[2] = __float_as_uint(pa[4]);
            a[3] = __float_as_uint(pa[8 * PS_STRIDE + 4]);
#pragma unroll
            for (int nt = 0; nt < 16; nt++) {
                uint32_t bb[2];
                const float* vp = Vs + (kc * 8 + lr) * VS_STRIDE + nt * 8 + lq;
                bb[0] = __float_as_uint(vp[0]);
                bb[1] = __float_as_uint(vp[4 * VS_STRIDE]);
                mma_tf32(oacc[nt], a, bb);
            }
        }
    }

    // ---- epilogue: normalize + write to g_attn[tok][h*128+d] ----
    float inv0 = 1.f / l0, inv1 = 1.f / l1;
    size_t tok0 = (size_t)b * S_LEN + qb * 128 + rbaseQ;
    float* d0 = Out + tok0 * HID + h * 128 + 2 * lr;
    float* d1 = d0 + (size_t)8 * HID;
#pragma unroll
    for (int nt = 0; nt < 16; nt++) {
        float2 o0, o1;
        o0.x = oacc[nt][0] * inv0; o0.y = oacc[nt][1] * inv0;
        o1.x = oacc[nt][2] * inv1; o1.y = oacc[nt][3] * inv1;
        *(float2*)(d0 + nt * 8) = o0;
        *(float2*)(d1 + nt * 8) = o1;
    }
}

// ---------------- launch ----------------
extern "C" void kernel_launch(void* const* d_in, const int* in_sizes, int n_in,
                              void* d_out, int out_size) {
    const float* X  = (const float*)d_in[0];
    const float* cs = (const float*)d_in[1];
    const float* sn = (const float*)d_in[2];
    // d_in[3] attention_mask: pure causal, handled analytically
    const float* Wq = (const float*)d_in[4];
    const float* bq = (const float*)d_in[5];
    const float* Wk = (const float*)d_in[6];
    const float* bk = (const float*)d_in[7];
    const float* Wv = (const float*)d_in[8];
    const float* bv = (const float*)d_in[9];
    const float* Wo = (const float*)d_in[10];
    float* out = (float*)d_out;

    float *Qp, *Kp, *Vp, *Ap;
    cudaGetSymbolAddress((void**)&Qp, g_Q);
    cudaGetSymbolAddress((void**)&Kp, g_K);
    cudaGetSymbolAddress((void**)&Vp, g_V);
    cudaGetSymbolAddress((void**)&Ap, g_attn);

    cudaFuncSetAttribute(flash_attn_tc, cudaFuncAttributeMaxDynamicSharedMemorySize,
                         FLASH_SMEM_BYTES);

    gemm_tf32<1><<<dim3(HID / 128, M_TOK / 128), 256>>>(X, Wq, bq, Qp, M_TOK, HID, HID);
    gemm_tf32<1><<<dim3(512 / 128, M_TOK / 128), 256>>>(X, Wk, bk, Kp, M_TOK, 512, HID);
    gemm_tf32<1><<<dim3(512 / 128, M_TOK / 128), 256>>>(X, Wv, bv, Vp, M_TOK, 512, HID);

    rope_kernel<<<(BATCH * NH * S_LEN * 64) / 256, 256>>>(Qp, cs, sn, NH);
    rope_kernel<<<(BATCH * NKV * S_LEN * 64) / 256, 256>>>(Kp, cs, sn, NKV);

    flash_attn_tc<<<dim3(S_LEN / 128, NH, BATCH), 256, FLASH_SMEM_BYTES>>>(Qp, Kp, Vp, Ap);

    gemm_tf32<0><<<dim3(HID / 128, M_TOK / 128), 256>>>(Ap, Wo, nullptr, out, M_TOK, HID, HID);
}

// round 3
// speedup vs baseline: 2.3156x; 1.1859x over previous
#include <cuda_runtime.h>
#include <cstdint>
#include <cstddef>

#define S_LEN   2048
#define HID     3584
#define NH      28
#define NKV     4
#define HD      128
#define BATCH   2
#define M_TOK   (BATCH * S_LEN)      // 4096
#define SCALE_Q 0.08838834764831845f // 1/sqrt(128)

// ---------------- scratch (no allocation allowed) ----------------
__device__ float g_Q[(size_t)BATCH * NH * S_LEN * HD];
__device__ float g_K[(size_t)BATCH * NKV * S_LEN * HD];
__device__ float g_V[(size_t)BATCH * NKV * S_LEN * HD];
__device__ float g_attn[(size_t)M_TOK * HID];
__device__ float g_Xr[(size_t)M_TOK * HID];
__device__ float g_Wqr[(size_t)NH * HD * HID];
__device__ float g_Wkr[(size_t)NKV * HD * HID];
__device__ float g_Wvr[(size_t)NKV * HD * HID];
__device__ float g_Wor[(size_t)HID * NH * HD];

// ---------------- helpers ----------------
__device__ __forceinline__ uint32_t f2tf32(float x) {
    uint32_t r;
    asm("cvt.rna.tf32.f32 %0, %1;" : "=r"(r) : "f"(x));
    return r;
}

__device__ __forceinline__ void mma_tf32(float* c, const uint32_t* a, const uint32_t* b) {
    asm volatile(
        "mma.sync.aligned.m16n8k8.row.col.f32.tf32.tf32.f32 "
        "{%0,%1,%2,%3},{%4,%5,%6,%7},{%8,%9},{%0,%1,%2,%3};"
        : "+f"(c[0]), "+f"(c[1]), "+f"(c[2]), "+f"(c[3])
        : "r"(a[0]), "r"(a[1]), "r"(a[2]), "r"(a[3]), "r"(b[0]), "r"(b[1]));
}

__device__ __forceinline__ void cp_async16(float* smem_dst, const float* gsrc) {
    uint32_t s;
    asm("{ .reg .u64 t; cvta.to.shared.u64 t, %1; cvt.u32.u64 %0, t; }"
        : "=r"(s) : "l"(smem_dst));
    asm volatile("cp.async.cg.shared.global [%0], [%1], 16;" :: "r"(s), "l"(gsrc));
}
#define CP_COMMIT() asm volatile("cp.async.commit_group;")
#define CP_WAIT(N)  asm volatile("cp.async.wait_group %0;" :: "n"(N))

// ---------------- tf32 pre-round (vectorized) ----------------
__global__ void round_tf32_kernel(const float4* __restrict__ src,
                                  float4* __restrict__ dst, int n4) {
    int i = blockIdx.x * blockDim.x + threadIdx.x;
    if (i < n4) {
        float4 v = src[i];
        float4 o;
        o.x = __uint_as_float(f2tf32(v.x));
        o.y = __uint_as_float(f2tf32(v.y));
        o.z = __uint_as_float(f2tf32(v.z));
        o.w = __uint_as_float(f2tf32(v.w));
        dst[i] = o;
    }
}

// ---------------- pipelined GEMM: C = A * Bw^T + bias (inputs pre-rounded) ----
// OUT_MODE 0: C[m*N+n] (fp32). OUT_MODE 1: head layout, value tf32-rounded.
#define GK_CHUNKS (HID / 32)  // 112
template <int OUT_MODE>
__global__ __launch_bounds__(256, 2)
void gemm_tf32_pipe(const float* __restrict__ A, const float* __restrict__ Bw,
                    const float* __restrict__ bias, float* __restrict__ C,
                    int M, int N, int K) {
    extern __shared__ float gsm[];
    float* As = gsm;                 // [2][128][36]
    float* Bs = gsm + 2 * 128 * 36;  // [2][128][36]

    const int tid  = threadIdx.x;
    const int warp = tid >> 5;
    const int lane = tid & 31;
    const int wm   = warp >> 1;
    const int wn   = warp & 1;
    const int bm   = blockIdx.y * 128;
    const int bn   = blockIdx.x * 128;
    const int lrow = tid >> 3, lc4 = tid & 7;  // loader coords (4 iters of 32 rows)

    const float* Ab = A + (size_t)(bm + lrow) * K + lc4 * 4;
    const float* Bb = Bw + (size_t)(bn + lrow) * K + lc4 * 4;

    float acc[2][8][4];
#pragma unroll
    for (int mt = 0; mt < 2; mt++)
#pragma unroll
        for (int nt = 0; nt < 8; nt++)
#pragma unroll
            for (int i = 0; i < 4; i++) acc[mt][nt][i] = 0.f;

    // prologue: issue chunks 0,1
#pragma unroll
    for (int s = 0; s < 2; s++) {
        float* dA = As + s * (128 * 36);
        float* dB = Bs + s * (128 * 36);
#pragma unroll
        for (int i = 0; i < 4; i++) {
            cp_async16(dA + (lrow + i * 32) * 36 + lc4 * 4, Ab + (size_t)(i * 32) * K + s * 32);
            cp_async16(dB + (lrow + i * 32) * 36 + lc4 * 4, Bb + (size_t)(i * 32) * K + s * 32);
        }
        CP_COMMIT();
    }

    for (int k = 0; k < GK_CHUNKS; k++) {
        if (k + 1 < GK_CHUNKS) { CP_WAIT(1); } else { CP_WAIT(0); }
        __syncthreads();

        const float* Ac = As + (k & 1) * (128 * 36);
        const float* Bc = Bs + (k & 1) * (128 * 36);
#pragma unroll
        for (int kk = 0; kk < 32; kk += 8) {
            uint32_t aF[2][4], bF[8][2];
#pragma unroll
            for (int mt = 0; mt < 2; mt++) {
                const float* ap = Ac + (wm * 32 + mt * 16 + (lane >> 2)) * 36 + kk + (lane & 3);
                aF[mt][0] = __float_as_uint(ap[0]);
                aF[mt][1] = __float_as_uint(ap[8 * 36]);
                aF[mt][2] = __float_as_uint(ap[4]);
                aF[mt][3] = __float_as_uint(ap[8 * 36 + 4]);
            }
#pragma unroll
            for (int nt = 0; nt < 8; nt++) {
                const float* bp = Bc + (wn * 64 + nt * 8 + (lane >> 2)) * 36 + kk + (lane & 3);
                bF[nt][0] = __float_as_uint(bp[0]);
                bF[nt][1] = __float_as_uint(bp[4]);
            }
#pragma unroll
            for (int mt = 0; mt < 2; mt++)
#pragma unroll
                for (int nt = 0; nt < 8; nt++)
                    mma_tf32(acc[mt][nt], aF[mt], bF[nt]);
        }
        __syncthreads();

        if (k + 2 < GK_CHUNKS) {
            float* dA = As + (k & 1) * (128 * 36);
            float* dB = Bs + (k & 1) * (128 * 36);
            int k0 = (k + 2) * 32;
#pragma unroll
            for (int i = 0; i < 4; i++) {
                cp_async16(dA + (lrow + i * 32) * 36 + lc4 * 4, Ab + (size_t)(i * 32) * K + k0);
                cp_async16(dB + (lrow + i * 32) * 36 + lc4 * 4, Bb + (size_t)(i * 32) * K + k0);
            }
            CP_COMMIT();
        }
    }

#pragma unroll
    for (int mt = 0; mt < 2; mt++) {
        int rbase = bm + wm * 32 + mt * 16 + (lane >> 2);
#pragma unroll
        for (int nt = 0; nt < 8; nt++) {
            int cbase = bn + wn * 64 + nt * 8 + ((lane & 3) << 1);
#pragma unroll
            for (int e = 0; e < 4; e++) {
                int r = rbase + ((e >> 1) << 3);
                int c = cbase + (e & 1);
                float v = acc[mt][nt][e];
                if (bias) v += bias[c];
                if (OUT_MODE == 0) {
                    C[(size_t)r * N + c] = v;
                } else {
                    v = __uint_as_float(f2tf32(v));
                    int b = r >> 11, s = r & 2047;
                    int h = c >> 7, d = c & 127;
                    C[((((size_t)b * (N >> 7) + h) * 2048 + s) << 7) + d] = v;
                }
            }
        }
    }
}

// ---------------- RoPE (in-place, folds scale, writes tf32-rounded) --------
__global__ void rope_kernel(float* __restrict__ X, const float* __restrict__ cs,
                            const float* __restrict__ sn, int HX, float scale) {
    int idx = blockIdx.x * blockDim.x + threadIdx.x;
    int d  = idx & 63;
    int s  = (idx >> 6) & (S_LEN - 1);
    int bh = idx >> 17;
    int b  = bh / HX;
    int ci = ((b << 11) + s) * 128 + d;
    float c  = cs[ci];
    float si = sn[ci];
    float* p = X + (((size_t)bh << 11) + s) * 128 + d;
    float x1 = p[0], x2 = p[64];
    p[0]  = __uint_as_float(f2tf32((x1 * c - x2 * si) * scale));
    p[64] = __uint_as_float(f2tf32((x2 * c + x1 * si) * scale));
}

// ---------------- tensor-core flash attention (pipelined) -------------------
// smem floats: Qs[128][132]@0, Ks[2][64][132]@16896, Vs[64][136]@33792, Ps[128][68]@42496
#define QS_STRIDE 132
#define KS_STRIDE 132
#define VS_STRIDE 136
#define PS_STRIDE 68
#define KS_OFF    16896
#define KS_STG    (64 * 132)
#define VS_OFF    33792
#define PS_OFF    42496
#define FLASH_SMEM_BYTES ((42496 + 128 * 68) * 4)  // 204800

__global__ __launch_bounds__(256, 1)
void flash_attn_tc(const float* __restrict__ Q, const float* __restrict__ K,
                   const float* __restrict__ V, float* __restrict__ Out) {
    extern __shared__ float sm[];
    float* Qs = sm;
    float* Ks = sm + KS_OFF;
    float* Vs = sm + VS_OFF;
    float* Ps = sm + PS_OFF;

    const int qb  = (gridDim.x - 1) - blockIdx.x;  // heavy blocks first
    const int h   = blockIdx.y;
    const int b   = blockIdx.z;
    const int kvh = h / (NH / NKV);

    const int t    = threadIdx.x;
    const int w    = t >> 5;
    const int lane = t & 31;
    const int lq   = lane >> 2;
    const int lr   = lane & 3;

    const float* Qg = Q + ((((size_t)(b * NH + h) * S_LEN) + qb * 128) << 7);
    const float* Kg = K + (((size_t)(b * NKV + kvh) * S_LEN) << 7);
    const float* Vg = V + (((size_t)(b * NKV + kvh) * S_LEN) << 7);

    const int lrow8 = t >> 5, lc4 = t & 31;  // loader coords for 64x128 tiles

    // load Q tile (pre-scaled, pre-rounded): plain copy
#pragma unroll
    for (int i = 0; i < 16; i++) {
        int f = i * 256 + t;
        int row = f >> 5, c4 = f & 31;
        *(float4*)(Qs + row * QS_STRIDE + c4 * 4) =
            *(const float4*)(Qg + (row << 7) + c4 * 4);
    }

    // prologue: issue K(0)
    {
        float* dK = Ks;
#pragma unroll
        for (int i = 0; i < 8; i++)
            cp_async16(dK + (lrow8 + i * 8) * KS_STRIDE + lc4 * 4,
                       Kg + ((size_t)(lrow8 + i * 8) << 7) + lc4 * 4);
        CP_COMMIT();
    }

    float m0 = -1e30f, m1 = -1e30f, l0 = 0.f, l1 = 0.f;
    float oacc[16][4];
#pragma unroll
    for (int nt = 0; nt < 16; nt++)
#pragma unroll
        for (int e = 0; e < 4; e++) oacc[nt][e] = 0.f;

    const int rbaseQ = w * 16 + lq;
    const int nkb = 2 * qb + 2;

    for (int kb = 0; kb < nkb; kb++) {
        CP_WAIT(0);          // K(kb) ready (previous V already waited)
        __syncthreads();     // visible to all; Vs free (PV(kb-1) done)

        // issue V(kb) — overlaps scores+softmax
        {
            const float* Vb = Vg + ((size_t)(kb * 64) << 7);
#pragma unroll
            for (int i = 0; i < 8; i++)
                cp_async16(Vs + (lrow8 + i * 8) * VS_STRIDE + lc4 * 4,
                           Vb + ((size_t)(lrow8 + i * 8) << 7) + lc4 * 4);
            CP_COMMIT();
        }
        // issue K(kb+1) — overlaps rest of iteration
        if (kb + 1 < nkb) {
            const float* Kb = Kg + ((size_t)((kb + 1) * 64) << 7);
            float* dK = Ks + ((kb + 1) & 1) * KS_STG;
#pragma unroll
            for (int i = 0; i < 8; i++)
                cp_async16(dK + (lrow8 + i * 8) * KS_STRIDE + lc4 * 4,
                           Kb + ((size_t)(lrow8 + i * 8) << 7) + lc4 * 4);
            CP_COMMIT();
        }

        // ---- scores ----
        const float* Kc = Ks + (kb & 1) * KS_STG;
        float sacc[8][4];
#pragma unroll
        for (int nt = 0; nt < 8; nt++)
#pragma unroll
            for (int e = 0; e < 4; e++) sacc[nt][e] = 0.f;

#pragma unroll
        for (int kc = 0; kc < 16; kc++) {
            uint32_t a[4];
            const float* qp = Qs + rbaseQ * QS_STRIDE + kc * 8 + lr;
            a[0] = __float_as_uint(qp[0]);
            a[1] = __float_as_uint(qp[8 * QS_STRIDE]);
            a[2] = __float_as_uint(qp[4]);
            a[3] = __float_as_uint(qp[8 * QS_STRIDE + 4]);
#pragma unroll
            for (int nt = 0; nt < 8; nt++) {
                uint32_t bb[2];
                const float* kp = Kc + (nt * 8 + lq) * KS_STRIDE + kc * 8 + lr;
                bb[0] = __float_as_uint(kp[0]);
                bb[1] = __float_as_uint(kp[4]);
                mma_tf32(sacc[nt], a, bb);
            }
        }

        if (kb >= 2 * qb) {  // causal mask near diagonal
            int row0 = qb * 128 + rbaseQ;
#pragma unroll
            for (int nt = 0; nt < 8; nt++) {
                int key = kb * 64 + nt * 8 + lr * 2;
                if (key     > row0)     sacc[nt][0] = -1e30f;
                if (key + 1 > row0)     sacc[nt][1] = -1e30f;
                if (key     > row0 + 8) sacc[nt][2] = -1e30f;
                if (key + 1 > row0 + 8) sacc[nt][3] = -1e30f;
            }
        }

        // ---- online softmax ----
        float mx0 = -1e30f, mx1 = -1e30f;
#pragma unroll
        for (int nt = 0; nt < 8; nt++) {
            mx0 = fmaxf(mx0, fmaxf(sacc[nt][0], sacc[nt][1]));
            mx1 = fmaxf(mx1, fmaxf(sacc[nt][2], sacc[nt][3]));
        }
        mx0 = fmaxf(mx0, __shfl_xor_sync(0xffffffffu, mx0, 1));
        mx0 = fmaxf(mx0, __shfl_xor_sync(0xffffffffu, mx0, 2));
        mx1 = fmaxf(mx1, __shfl_xor_sync(0xffffffffu, mx1, 1));
        mx1 = fmaxf(mx1, __shfl_xor_sync(0xffffffffu, mx1, 2));

        float mn0 = fmaxf(m0, mx0), mn1 = fmaxf(m1, mx1);
        float al0 = __expf(m0 - mn0), al1 = __expf(m1 - mn1);
        m0 = mn0; m1 = mn1;

        float s0 = 0.f, s1 = 0.f;
        float* pp0 = Ps + rbaseQ * PS_STRIDE + 2 * lr;
        float* pp1 = pp0 + 8 * PS_STRIDE;
#pragma unroll
        for (int nt = 0; nt < 8; nt++) {
            float p00 = __expf(sacc[nt][0] - mn0);
            float p01 = __expf(sacc[nt][1] - mn0);
            float p10 = __expf(sacc[nt][2] - mn1);
            float p11 = __expf(sacc[nt][3] - mn1);
            s0 += p00 + p01;
            s1 += p10 + p11;
            float2 q0, q1;
            q0.x = __uint_as_float(f2tf32(p00)); q0.y = __uint_as_float(f2tf32(p01));
            q1.x = __uint_as_float(f2tf32(p10)); q1.y = __uint_as_float(f2tf32(p11));
            *(float2*)(pp0 + nt * 8) = q0;
            *(float2*)(pp1 + nt * 8) = q1;
        }
        s0 += __shfl_xor_sync(0xffffffffu, s0, 1);
        s0 += __shfl_xor_sync(0xffffffffu, s0, 2);
        s1 += __shfl_xor_sync(0xffffffffu, s1, 1);
        s1 += __shfl_xor_sync(0xffffffffu, s1, 2);
        l0 = l0 * al0 + s0;
        l1 = l1 * al1 + s1;

#pragma unroll
        for (int nt = 0; nt < 16; nt++) {
            oacc[nt][0] *= al0; oacc[nt][1] *= al0;
            oacc[nt][2] *= al1; oacc[nt][3] *= al1;
        }

        if (kb + 1 < nkb) { CP_WAIT(1); } else { CP_WAIT(0); }  // V(kb) done
        __syncthreads();   // Ps + Vs visible

        // ---- PV ----
#pragma unroll
        for (int kc = 0; kc < 8; kc++) {
            uint32_t a[4];
            const float* pa = Ps + rbaseQ * PS_STRIDE + kc * 8 + lr;
            a[0] = __float_as_uint(pa[0]);
            a[1] = __float_as_uint(pa[8 * PS_STRIDE]);
            a[2] = __float_as_uint(pa[4]);
            a[3] = __float_as_uint(pa[8 * PS_STRIDE + 4]);
#pragma unroll
            for (int nt = 0; nt < 16; nt++) {
                uint32_t bb[2];
                const float* vp = Vs + (kc * 8 + lr) * VS_STRIDE + nt * 8 + lq;
                bb[0] = __float_as_uint(vp[0]);
                bb[1] = __float_as_uint(vp[4 * VS_STRIDE]);
                mma_tf32(oacc[nt], a, bb);
            }
        }
    }

    // ---- epilogue: normalize + round (tf32) for the O-GEMM ----
    float inv0 = 1.f / l0, inv1 = 1.f / l1;
    size_t tok0 = (size_t)b * S_LEN + qb * 128 + rbaseQ;
    float* d0 = Out + tok0 * HID + h * 128 + 2 * lr;
    float* d1 = d0 + (size_t)8 * HID;
#pragma unroll
    for (int nt = 0; nt < 16; nt++) {
        float2 o0, o1;
        o0.x = __uint_as_float(f2tf32(oacc[nt][0] * inv0));
        o0.y = __uint_as_float(f2tf32(oacc[nt][1] * inv0));
        o1.x = __uint_as_float(f2tf32(oacc[nt][2] * inv1));
        o1.y = __uint_as_float(f2tf32(oacc[nt][3] * inv1));
        *(float2*)(d0 + nt * 8) = o0;
        *(float2*)(d1 + nt * 8) = o1;
    }
}

// ---------------- launch ----------------
#define GEMM_SMEM_BYTES (2 * 2 * 128 * 36 * 4)  // 73728

extern "C" void kernel_launch(void* const* d_in, const int* in_sizes, int n_in,
                              void* d_out, int out_size) {
    const float* X  = (const float*)d_in[0];
    const float* cs = (const float*)d_in[1];
    const float* sn = (const float*)d_in[2];
    // d_in[3] attention_mask: pure causal, handled analytically
    const float* Wq = (const float*)d_in[4];
    const float* bq = (const float*)d_in[5];
    const float* Wk = (const float*)d_in[6];
    const float* bk = (const float*)d_in[7];
    const float* Wv = (const float*)d_in[8];
    const float* bv = (const float*)d_in[9];
    const float* Wo = (const float*)d_in[10];
    float* out = (float*)d_out;

    float *Qp, *Kp, *Vp, *Ap, *Xr, *Wqr, *Wkr, *Wvr, *Wor;
    cudaGetSymbolAddress((void**)&Qp, g_Q);
    cudaGetSymbolAddress((void**)&Kp, g_K);
    cudaGetSymbolAddress((void**)&Vp, g_V);
    cudaGetSymbolAddress((void**)&Ap, g_attn);
    cudaGetSymbolAddress((void**)&Xr, g_Xr);
    cudaGetSymbolAddress((void**)&Wqr, g_Wqr);
    cudaGetSymbolAddress((void**)&Wkr, g_Wkr);
    cudaGetSymbolAddress((void**)&Wvr, g_Wvr);
    cudaGetSymbolAddress((void**)&Wor, g_Wor);

    cudaFuncSetAttribute(flash_attn_tc, cudaFuncAttributeMaxDynamicSharedMemorySize,
                         FLASH_SMEM_BYTES);
    cudaFuncSetAttribute(gemm_tf32_pipe<0>, cudaFuncAttributeMaxDynamicSharedMemorySize,
                         GEMM_SMEM_BYTES);
    cudaFuncSetAttribute(gemm_tf32_pipe<1>, cudaFuncAttributeMaxDynamicSharedMemorySize,
                         GEMM_SMEM_BYTES);

    // pre-round inputs to tf32-exact fp32
    auto rnd = [](const float* s, float* d, size_t n) {
        int n4 = (int)(n / 4);
        round_tf32_kernel<<<(n4 + 255) / 256, 256>>>((const float4*)s, (float4*)d, n4);
    };
    rnd(X,  Xr,  (size_t)M_TOK * HID);
    rnd(Wq, Wqr, (size_t)NH * HD * HID);
    rnd(Wk, Wkr, (size_t)NKV * HD * HID);
    rnd(Wv, Wvr, (size_t)NKV * HD * HID);
    rnd(Wo, Wor, (size_t)HID * NH * HD);

    gemm_tf32_pipe<1><<<dim3(HID / 128, M_TOK / 128), 256, GEMM_SMEM_BYTES>>>(
        Xr, Wqr, bq, Qp, M_TOK, HID, HID);
    gemm_tf32_pipe<1><<<dim3(512 / 128, M_TOK / 128), 256, GEMM_SMEM_BYTES>>>(
        Xr, Wkr, bk, Kp, M_TOK, 512, HID);
    gemm_tf32_pipe<1><<<dim3(512 / 128, M_TOK / 128), 256, GEMM_SMEM_BYTES>>>(
        Xr, Wvr, bv, Vp, M_TOK, 512, HID);

    rope_kernel<<<(BATCH * NH * S_LEN * 64) / 256, 256>>>(Qp, cs, sn, NH, SCALE_Q);
    rope_kernel<<<(BATCH * NKV * S_LEN * 64) / 256, 256>>>(Kp, cs, sn, NKV, 1.0f);

    flash_attn_tc<<<dim3(S_LEN / 128, NH, BATCH), 256, FLASH_SMEM_BYTES>>>(Qp, Kp, Vp, Ap);

    gemm_tf32_pipe<0><<<dim3(HID / 128, M_TOK / 128), 256, GEMM_SMEM_BYTES>>>(
        Ap, Wor, nullptr, out, M_TOK, HID, HID);
}